// round 13
// baseline (speedup 1.0000x reference)
#include <cuda_runtime.h>
#include <cuda_fp16.h>
#include <cstdint>

#define BB 32
#define SS 512
#define DD 1024

// ---- device scratch (module-load allocated; no runtime allocs) ----
// E normalized fp16: [row][k] contiguous (2048B per row)
__device__ unsigned short g_eh[(size_t)BB * SS * DD];       // 32 MB
// aspect parity copies fp16: per batch 16 buffers x 2056 u16 (4112 B):
//   buf (h*8+p), h=0 hi / h=1 lo: buf[x] = a2_h[x + p], x in [0,2048)
__device__ __align__(16) unsigned short g_asp16[BB * 16 * 2056];  // 4.2 MB

// ============================ helpers ============================
__device__ __forceinline__ uint32_t smem_u32(const void* p) {
    uint32_t a;
    asm("{ .reg .u64 t; cvta.to.shared.u64 t, %1; cvt.u32.u64 %0, t; }" : "=r"(a) : "l"(p));
    return a;
}
__device__ __forceinline__ void cpasync16(uint32_t dst, const void* src) {
    asm volatile("cp.async.cg.shared.global [%0], [%1], 16;" :: "r"(dst), "l"(src));
}
__device__ __forceinline__ void ldsm4(uint32_t* r, uint32_t a) {
    asm volatile("ldmatrix.sync.aligned.m8n8.x4.shared.b16 {%0,%1,%2,%3}, [%4];"
                 : "=r"(r[0]), "=r"(r[1]), "=r"(r[2]), "=r"(r[3]) : "r"(a));
}
__device__ __forceinline__ void mma16816(float* c, const uint32_t* a, const uint32_t* b) {
    asm volatile(
        "mma.sync.aligned.m16n8k16.row.col.f32.f16.f16.f32 "
        "{%0,%1,%2,%3}, {%4,%5,%6,%7}, {%8,%9}, {%0,%1,%2,%3};"
        : "+f"(c[0]), "+f"(c[1]), "+f"(c[2]), "+f"(c[3])
        : "r"(a[0]), "r"(a[1]), "r"(a[2]), "r"(a[3]), "r"(b[0]), "r"(b[1]));
}

// ============================ prep kernel (fused) ============================
__global__ void prep_kernel(const float* __restrict__ e, const float* __restrict__ a) {
    int bx = blockIdx.x, b = blockIdx.y, t = threadIdx.x;  // 256 threads
    const float* src = (bx < SS) ? (e + ((size_t)b * SS + bx) * DD)
                                 : (a + (size_t)b * DD);
    float4 v = ((const float4*)src)[t];
    float sum = v.x * v.x + v.y * v.y + v.z * v.z + v.w * v.w;
    #pragma unroll
    for (int o = 16; o; o >>= 1) sum += __shfl_xor_sync(0xffffffffu, sum, o);
    __shared__ float ws[8];
    __shared__ float s_inv;
    if ((t & 31) == 0) ws[t >> 5] = sum;
    __syncthreads();
    if (t == 0) {
        float tot = 0.f;
        #pragma unroll
        for (int i = 0; i < 8; i++) tot += ws[i];
        s_inv = (tot > 0.f) ? rsqrtf(tot) : 0.f;
    }
    __syncthreads();
    float inv = s_inv;
    float n[4] = {v.x * inv, v.y * inv, v.z * inv, v.w * inv};

    if (bx < SS) {
        ushort4 ph;
        unsigned short* hp = &ph.x;
        #pragma unroll
        for (int j = 0; j < 4; j++)
            hp[j] = __half_as_ushort(__float2half(n[j]));
        ((ushort4*)(g_eh + ((size_t)b * SS + bx) * DD))[t] = ph;
    } else {
        unsigned short* base = g_asp16 + (size_t)b * 16 * 2056;
        #pragma unroll
        for (int j = 0; j < 4; j++) {
            __half h = __float2half(n[j]);
            __half l = __float2half(n[j] - __half2float(h));
            unsigned short hu = __half_as_ushort(h);
            unsigned short lu = __half_as_ushort(l);
            int eidx = 4 * t + j;
            #pragma unroll
            for (int p = 0; p < 8; p++) {
                int x0 = eidx - p;
                unsigned short* bh = base + p * 2056;
                unsigned short* bl = base + (8 + p) * 2056;
                if (x0 >= 0) { bh[x0] = hu; bl[x0] = lu; }
                int x1 = x0 + 1024;
                if (x1 < 2048) { bh[x1] = hu; bl[x1] = lu; }
            }
        }
    }
}

// ============================ GEMM kernel ============================
// Persistent: 296 CTAs, each owns 3-4 consecutive tiles (same batch mostly).
// Per tile: out[b, s_base+m, i_base+n] = sum_k E[m][k]*Circ[n][k], fp16 hi+lo B
// read directly from parity aspect copies. CTA tile 128x128, 256 thr,
// warp 64x32, k-chunk 64, 2-stage A ring, 2 CTAs/SM.
#define ROWA 144                 // 128B payload + 16B pad
#define ASTG (128 * ROWA)        // 18432 per A stage
#define OFF_ASP (2 * ASTG)       // 36864
#define BUFS 4112                // parity buffer stride (bytes)
#define SMEM_DYN (OFF_ASP + 16 * BUFS)   // 102656
#define NCHUNK 16                // 1024 / 64
#define NCTA 296
#define BIGS 136                 // first BIGS CTAs take 4 tiles, rest 3

__global__ void __launch_bounds__(256, 2) gemm_kernel(float* __restrict__ out) {
    extern __shared__ __align__(128) char smem[];
    const uint32_t sbase = smem_u32(smem);
    const uint32_t sAsp = sbase + OFF_ASP;

    const int j = blockIdx.x;
    int t0, ntile;
    if (j < BIGS) { t0 = 4 * j; ntile = 4; }
    else          { t0 = 4 * BIGS + 3 * (j - BIGS); ntile = 3; }

    const int tid  = threadIdx.x;
    const int wid  = tid >> 5;
    const int lane = tid & 31;
    const int wm = wid & 1;      // 2 m-groups of 64
    const int wn = wid >> 1;     // 4 n-groups of 32

    // A loader: thread covers row tid>>1, 64B half (tid&1)
    const int r0 = tid >> 1;
    const int h64 = (tid & 1) * 64;
    const uint32_t drowA = sbase + (uint32_t)r0 * ROWA + h64;

    // ldmatrix lane offsets (tile-independent parts)
    const uint32_t a_lane = (uint32_t)(wm * 64 + (lane & 15)) * ROWA + (lane >> 4) * 16;
    const int b_nsub = (lane & 7) + 8 * (lane >> 4);   // n sub-index within 16-group
    const int b_kb   = ((lane >> 3) & 1) * 8;          // k byte-half selector
    const uint32_t LO = 8 * BUFS;

    #define ISSUE_A0(P) do {                                            \
        const char* s_ = (P);                                           \
        cpasync16(drowA,      s_);                                      \
        cpasync16(drowA + 16, s_ + 16);                                 \
        cpasync16(drowA + 32, s_ + 32);                                 \
        cpasync16(drowA + 48, s_ + 48);                                 \
    } while (0)
    #define LOAD_A(ST, KC, P) do {                                      \
        uint32_t d_ = drowA + (ST) * ASTG;                              \
        const char* s_ = (P) + (size_t)(KC) * 128;                      \
        cpasync16(d_,      s_);                                         \
        cpasync16(d_ + 16, s_ + 16);                                    \
        cpasync16(d_ + 32, s_ + 32);                                    \
        cpasync16(d_ + 48, s_ + 48);                                    \
        asm volatile("cp.async.commit_group;");                         \
    } while (0)

    int cur_b = -1;
    int a0_done = 0;
    const char* pA_next = 0;

    for (int ti = 0; ti < ntile; ti++) {
        const int T = t0 + ti;
        const int b = T >> 5;
        const int i_base = (T & 7) * 128;
        const int s_base = ((T >> 3) & 3) * 128;

        const char* pA = (const char*)g_eh
            + ((size_t)b * SS + s_base + r0) * 2048 + h64;

        // B direct ldmatrix base addresses for this tile
        uint32_t bA[2];
        #pragma unroll
        for (int p = 0; p < 2; p++) {
            int s0 = DD + b_kb - (i_base + wn * 32 + p * 16 + b_nsub);  // >= 1
            bA[p] = sAsp + (uint32_t)(s0 & 7) * BUFS + (uint32_t)((s0 >> 3) << 4);
        }

        // ---- tile prologue ----
        if (b != cur_b) {
            __syncthreads();    // all warps done reading old aspect
            const char* pAsp = (const char*)g_asp16 + (size_t)b * 16 * BUFS;
            for (int q = tid; q < 16 * BUFS / 16; q += 256)
                cpasync16(sAsp + q * 16, pAsp + (size_t)q * 16);
            cur_b = b;
            a0_done = 0;        // prefetched A0 (if any) was for this tile anyway only when same batch
        }
        if (!a0_done) ISSUE_A0(pA);
        asm volatile("cp.async.commit_group;");
        asm volatile("cp.async.wait_group 0;" ::: "memory");
        __syncthreads();

        float acc[4][4][4];
        #pragma unroll
        for (int mt = 0; mt < 4; mt++)
            #pragma unroll
            for (int nt = 0; nt < 4; nt++)
                #pragma unroll
                for (int q = 0; q < 4; q++) acc[mt][nt][q] = 0.f;

        // ---- mainloop ----
        uint32_t bcoff = 0;
        #pragma unroll 2
        for (int c = 0; c < NCHUNK; c++) {
            if (c + 1 < NCHUNK) LOAD_A((c + 1) & 1, c + 1, pA);

            const uint32_t sa = sbase + (c & 1) * ASTG;

            #pragma unroll
            for (int kk = 0; kk < 4; kk++) {
                const uint32_t akb = (uint32_t)(kk * 32);
                const uint32_t bkk = bcoff + (uint32_t)(kk * 32);
                uint32_t aH[4][4], bH[2][4], bL[2][4];
                #pragma unroll
                for (int mt = 0; mt < 4; mt++)
                    ldsm4(aH[mt], sa + a_lane + mt * 16 * ROWA + akb);
                #pragma unroll
                for (int p = 0; p < 2; p++)
                    ldsm4(bH[p], bA[p] + bkk);
                #pragma unroll
                for (int p = 0; p < 2; p++)
                    ldsm4(bL[p], bA[p] + LO + bkk);
                #pragma unroll
                for (int mt = 0; mt < 4; mt++)
                    #pragma unroll
                    for (int nt = 0; nt < 4; nt++)
                        mma16816(acc[mt][nt], aH[mt], &bH[nt >> 1][2 * (nt & 1)]);
                #pragma unroll
                for (int mt = 0; mt < 4; mt++)
                    #pragma unroll
                    for (int nt = 0; nt < 4; nt++)
                        mma16816(acc[mt][nt], aH[mt], &bL[nt >> 1][2 * (nt & 1)]);
            }
            bcoff += 128;

            if (c + 1 < NCHUNK) {
                asm volatile("cp.async.wait_group 0;" ::: "memory");
                __syncthreads();
            }
        }

        // ---- prefetch next tile's A0 (stage 0 is free) ----
        a0_done = 0;
        if (ti + 1 < ntile && ((t0 + ti + 1) >> 5) == b) {
            const int Tn = t0 + ti + 1;
            const int sbn = ((Tn >> 3) & 3) * 128;
            pA_next = (const char*)g_eh + ((size_t)b * SS + sbn + r0) * 2048 + h64;
            ISSUE_A0(pA_next);
            asm volatile("cp.async.commit_group;");
            a0_done = 1;
        }

        // ---- epilogue: direct f32 stores ----
        #pragma unroll
        for (int mt = 0; mt < 4; mt++) {
            int rr = s_base + wm * 64 + mt * 16 + (lane >> 2);
            float* p0 = out + ((size_t)b * SS + rr) * DD + i_base + wn * 32 + (lane & 3) * 2;
            float* p1 = p0 + (size_t)8 * DD;
            #pragma unroll
            for (int nt = 0; nt < 4; nt++) {
                *(float2*)(p0 + nt * 8) = make_float2(acc[mt][nt][0], acc[mt][nt][1]);
                *(float2*)(p1 + nt * 8) = make_float2(acc[mt][nt][2], acc[mt][nt][3]);
            }
        }
    }
}

// ============================ launch ============================
extern "C" void kernel_launch(void* const* d_in, const int* in_sizes, int n_in,
                              void* d_out, int out_size) {
    const float* emb = (const float*)d_in[0];   // (32, 512, 1024) f32
    const float* asp = (const float*)d_in[1];   // (32, 1024) f32
    float* out = (float*)d_out;                 // (32, 512, 1024) f32

    cudaFuncSetAttribute(gemm_kernel, cudaFuncAttributeMaxDynamicSharedMemorySize, SMEM_DYN);

    prep_kernel<<<dim3(SS + 1, BB), 256>>>(emb, asp);
    gemm_kernel<<<NCTA, 256, SMEM_DYN>>>(out);
}

// round 14
// speedup vs baseline: 1.3232x; 1.3232x over previous
#include <cuda_runtime.h>
#include <cuda_fp16.h>
#include <cstdint>

#define BB 32
#define SS 512
#define DD 1024

// ---- device scratch (module-load allocated; no runtime allocs) ----
// E normalized fp16: [row][k] contiguous (2048B per row)
__device__ unsigned short g_eh[(size_t)BB * SS * DD];       // 32 MB
// aspect parity copies fp16 (hi only): per batch 8 buffers x 2056 u16:
//   buf p: buf[x] = a2[x + p], x in [0,2048), a2[y] = a_norm[y mod 1024]
__device__ __align__(16) unsigned short g_asp16[BB * 8 * 2056];  // 2.1 MB

// ============================ helpers ============================
__device__ __forceinline__ uint32_t smem_u32(const void* p) {
    uint32_t a;
    asm("{ .reg .u64 t; cvta.to.shared.u64 t, %1; cvt.u32.u64 %0, t; }" : "=r"(a) : "l"(p));
    return a;
}
__device__ __forceinline__ void cpasync16(uint32_t dst, const void* src) {
    asm volatile("cp.async.cg.shared.global [%0], [%1], 16;" :: "r"(dst), "l"(src));
}
__device__ __forceinline__ void ldsm4(uint32_t* r, uint32_t a) {
    asm volatile("ldmatrix.sync.aligned.m8n8.x4.shared.b16 {%0,%1,%2,%3}, [%4];"
                 : "=r"(r[0]), "=r"(r[1]), "=r"(r[2]), "=r"(r[3]) : "r"(a));
}
__device__ __forceinline__ void mma16816(float* c, const uint32_t* a, const uint32_t* b) {
    asm volatile(
        "mma.sync.aligned.m16n8k16.row.col.f32.f16.f16.f32 "
        "{%0,%1,%2,%3}, {%4,%5,%6,%7}, {%8,%9}, {%0,%1,%2,%3};"
        : "+f"(c[0]), "+f"(c[1]), "+f"(c[2]), "+f"(c[3])
        : "r"(a[0]), "r"(a[1]), "r"(a[2]), "r"(a[3]), "r"(b[0]), "r"(b[1]));
}

// ============================ prep kernel (fused) ============================
__global__ void prep_kernel(const float* __restrict__ e, const float* __restrict__ a) {
    int bx = blockIdx.x, b = blockIdx.y, t = threadIdx.x;  // 256 threads
    const float* src = (bx < SS) ? (e + ((size_t)b * SS + bx) * DD)
                                 : (a + (size_t)b * DD);
    float4 v = ((const float4*)src)[t];
    float sum = v.x * v.x + v.y * v.y + v.z * v.z + v.w * v.w;
    #pragma unroll
    for (int o = 16; o; o >>= 1) sum += __shfl_xor_sync(0xffffffffu, sum, o);
    __shared__ float ws[8];
    __shared__ float s_inv;
    if ((t & 31) == 0) ws[t >> 5] = sum;
    __syncthreads();
    if (t == 0) {
        float tot = 0.f;
        #pragma unroll
        for (int i = 0; i < 8; i++) tot += ws[i];
        s_inv = (tot > 0.f) ? rsqrtf(tot) : 0.f;
    }
    __syncthreads();
    float inv = s_inv;
    float n[4] = {v.x * inv, v.y * inv, v.z * inv, v.w * inv};

    if (bx < SS) {
        ushort4 ph;
        unsigned short* hp = &ph.x;
        #pragma unroll
        for (int j = 0; j < 4; j++)
            hp[j] = __half_as_ushort(__float2half(n[j]));
        ((ushort4*)(g_eh + ((size_t)b * SS + bx) * DD))[t] = ph;
    } else {
        unsigned short* base = g_asp16 + (size_t)b * 8 * 2056;
        #pragma unroll
        for (int j = 0; j < 4; j++) {
            unsigned short hu = __half_as_ushort(__float2half(n[j]));
            int eidx = 4 * t + j;
            #pragma unroll
            for (int p = 0; p < 8; p++) {
                int x0 = eidx - p;
                unsigned short* bh = base + p * 2056;
                if (x0 >= 0) bh[x0] = hu;
                int x1 = x0 + 1024;
                if (x1 < 2048) bh[x1] = hu;
            }
        }
    }
}

// ============================ GEMM kernel ============================
// out[b, s_base+m, i_base+n] = sum_k E[m][k] * Circ[n][k]  (single fp16 product)
// E fp16 (A ring), Circ fp16 ldsm'd DIRECTLY from parity aspect copies.
// CTA 128x128, 256 thr (8 warps, warp 64x32), k-chunk 128, 2 CTAs/SM.
#define ROWA 272                 // 256B payload + 16B pad
#define ASTG (128 * ROWA)        // 34816 per A stage
#define OFF_ASP (2 * ASTG)       // 69632
#define BUFS 4112                // parity buffer stride (bytes)
#define SMEM_DYN (OFF_ASP + 8 * BUFS)   // 102528
#define NCHUNK 8                 // 1024 / 128

__global__ void __launch_bounds__(256, 2) gemm_kernel(float* __restrict__ out) {
    extern __shared__ __align__(128) char smem[];
    const uint32_t sbase = smem_u32(smem);
    const uint32_t sAsp = sbase + OFF_ASP;

    const int b      = blockIdx.z;
    const int i_base = blockIdx.x * 128;
    const int s_base = blockIdx.y * 128;
    const int tid  = threadIdx.x;
    const int wid  = tid >> 5;
    const int lane = tid & 31;
    const int wm = wid & 1;      // 2 m-groups of 64
    const int wn = wid >> 1;     // 4 n-groups of 32

    // A loader: thread covers row tid>>1, 128B half (tid&1): 8 x 16B per chunk
    const int r0 = tid >> 1;
    const int h128 = (tid & 1) * 128;
    const char* pA = (const char*)g_eh + ((size_t)b * SS + s_base + r0) * 2048 + h128;
    const uint32_t drowA = sbase + (uint32_t)r0 * ROWA + h128;

    // A ldmatrix lane offset
    const uint32_t a_lane = (uint32_t)(wm * 64 + (lane & 15)) * ROWA + (lane >> 4) * 16;

    // B direct ldmatrix base addresses (lane-dependent, loop-invariant parity)
    uint32_t bA[2];
    #pragma unroll
    for (int p = 0; p < 2; p++) {
        int nidx = wn * 32 + p * 16 + (lane & 7) + 8 * (lane >> 4);
        int kb   = ((lane >> 3) & 1) * 8;
        int s0   = DD + kb - (i_base + nidx);      // >= 1
        int pp   = s0 & 7;
        bA[p] = sAsp + (uint32_t)pp * BUFS + (uint32_t)((s0 >> 3) << 4);
    }

    float acc[4][4][4];
    #pragma unroll
    for (int mt = 0; mt < 4; mt++)
        #pragma unroll
        for (int nt = 0; nt < 4; nt++)
            #pragma unroll
            for (int j = 0; j < 4; j++) acc[mt][nt][j] = 0.f;

    #define LOAD_A(ST, KC) do {                                         \
        uint32_t d_ = drowA + (ST) * ASTG;                              \
        const char* s_ = pA + (size_t)(KC) * 256;                       \
        cpasync16(d_,       s_);                                        \
        cpasync16(d_ + 16,  s_ + 16);                                   \
        cpasync16(d_ + 32,  s_ + 32);                                   \
        cpasync16(d_ + 48,  s_ + 48);                                   \
        cpasync16(d_ + 64,  s_ + 64);                                   \
        cpasync16(d_ + 80,  s_ + 80);                                   \
        cpasync16(d_ + 96,  s_ + 96);                                   \
        cpasync16(d_ + 112, s_ + 112);                                  \
        asm volatile("cp.async.commit_group;");                         \
    } while (0)

    // ---- prologue: aspect parity copies + A(0) ----
    {
        const char* pAsp = (const char*)g_asp16 + (size_t)b * 8 * BUFS;
        for (int j = tid; j < 8 * BUFS / 16; j += 256)
            cpasync16(sAsp + j * 16, pAsp + (size_t)j * 16);
    }
    LOAD_A(0, 0);
    asm volatile("cp.async.wait_group 0;" ::: "memory");
    __syncthreads();

    uint32_t bcoff = 0;   // B chunk byte offset (+256 per chunk)
    #pragma unroll 2
    for (int c = 0; c < NCHUNK; c++) {
        if (c + 1 < NCHUNK) LOAD_A((c + 1) & 1, c + 1);

        const uint32_t sa = sbase + (c & 1) * ASTG;

        #pragma unroll
        for (int kk = 0; kk < 8; kk++) {
            const uint32_t akb = (uint32_t)(kk * 32);
            const uint32_t bkk = bcoff + (uint32_t)(kk * 32);
            uint32_t aH[4][4], bH[2][4];
            #pragma unroll
            for (int mt = 0; mt < 4; mt++)
                ldsm4(aH[mt], sa + a_lane + mt * 16 * ROWA + akb);
            #pragma unroll
            for (int p = 0; p < 2; p++)
                ldsm4(bH[p], bA[p] + bkk);
            #pragma unroll
            for (int mt = 0; mt < 4; mt++)
                #pragma unroll
                for (int nt = 0; nt < 4; nt++)
                    mma16816(acc[mt][nt], aH[mt], &bH[nt >> 1][2 * (nt & 1)]);
        }
        bcoff += 256;

        if (c + 1 < NCHUNK) {
            asm volatile("cp.async.wait_group 0;" ::: "memory");
            __syncthreads();
        }
    }

    // ---- epilogue: direct f32 stores ----
    #pragma unroll
    for (int mt = 0; mt < 4; mt++) {
        int rr = s_base + wm * 64 + mt * 16 + (lane >> 2);
        float* p0 = out + ((size_t)b * SS + rr) * DD + i_base + wn * 32 + (lane & 3) * 2;
        float* p1 = p0 + (size_t)8 * DD;
        #pragma unroll
        for (int nt = 0; nt < 4; nt++) {
            *(float2*)(p0 + nt * 8) = make_float2(acc[mt][nt][0], acc[mt][nt][1]);
            *(float2*)(p1 + nt * 8) = make_float2(acc[mt][nt][2], acc[mt][nt][3]);
        }
    }
}

// ============================ launch ============================
extern "C" void kernel_launch(void* const* d_in, const int* in_sizes, int n_in,
                              void* d_out, int out_size) {
    const float* emb = (const float*)d_in[0];   // (32, 512, 1024) f32
    const float* asp = (const float*)d_in[1];   // (32, 1024) f32
    float* out = (float*)d_out;                 // (32, 512, 1024) f32

    cudaFuncSetAttribute(gemm_kernel, cudaFuncAttributeMaxDynamicSharedMemorySize, SMEM_DYN);

    prep_kernel<<<dim3(SS + 1, BB), 256>>>(emb, asp);
    gemm_kernel<<<dim3(DD / 128, SS / 128, BB), 256, SMEM_DYN>>>(out);
}

// round 16
// speedup vs baseline: 1.4031x; 1.0604x over previous
#include <cuda_runtime.h>
#include <cuda_fp16.h>
#include <cstdint>

#define BB 32
#define SS 512
#define DD 1024

// ---- device scratch (module-load allocated; no runtime allocs) ----
// E normalized fp16: [row][k] contiguous (2048B per row)
__device__ unsigned short g_eh[(size_t)BB * SS * DD];       // 32 MB
// aspect parity copies fp16 (hi only): per batch 8 buffers x 2056 u16:
//   buf p: buf[x] = a2[x + p], x in [0,2048), a2[y] = a_norm[y mod 1024]
__device__ __align__(16) unsigned short g_asp16[BB * 8 * 2056];  // 2.1 MB

// ============================ helpers ============================
__device__ __forceinline__ uint32_t smem_u32(const void* p) {
    uint32_t a;
    asm("{ .reg .u64 t; cvta.to.shared.u64 t, %1; cvt.u32.u64 %0, t; }" : "=r"(a) : "l"(p));
    return a;
}
__device__ __forceinline__ void cpasync16(uint32_t dst, const void* src) {
    asm volatile("cp.async.cg.shared.global [%0], [%1], 16;" :: "r"(dst), "l"(src));
}
__device__ __forceinline__ void ldsm4(uint32_t* r, uint32_t a) {
    asm volatile("ldmatrix.sync.aligned.m8n8.x4.shared.b16 {%0,%1,%2,%3}, [%4];"
                 : "=r"(r[0]), "=r"(r[1]), "=r"(r[2]), "=r"(r[3]) : "r"(a));
}
__device__ __forceinline__ void mma16816(float* c, const uint32_t* a, const uint32_t* b) {
    asm volatile(
        "mma.sync.aligned.m16n8k16.row.col.f32.f16.f16.f32 "
        "{%0,%1,%2,%3}, {%4,%5,%6,%7}, {%8,%9}, {%0,%1,%2,%3};"
        : "+f"(c[0]), "+f"(c[1]), "+f"(c[2]), "+f"(c[3])
        : "r"(a[0]), "r"(a[1]), "r"(a[2]), "r"(a[3]), "r"(b[0]), "r"(b[1]));
}

// ============================ prep kernel (fused) ============================
__global__ void prep_kernel(const float* __restrict__ e, const float* __restrict__ a) {
    int bx = blockIdx.x, b = blockIdx.y, t = threadIdx.x;  // 256 threads
    const float* src = (bx < SS) ? (e + ((size_t)b * SS + bx) * DD)
                                 : (a + (size_t)b * DD);
    float4 v = ((const float4*)src)[t];
    float sum = v.x * v.x + v.y * v.y + v.z * v.z + v.w * v.w;
    #pragma unroll
    for (int o = 16; o; o >>= 1) sum += __shfl_xor_sync(0xffffffffu, sum, o);
    __shared__ float ws[8];
    __shared__ float s_inv;
    if ((t & 31) == 0) ws[t >> 5] = sum;
    __syncthreads();
    if (t == 0) {
        float tot = 0.f;
        #pragma unroll
        for (int i = 0; i < 8; i++) tot += ws[i];
        s_inv = (tot > 0.f) ? rsqrtf(tot) : 0.f;
    }
    __syncthreads();
    float inv = s_inv;
    float n[4] = {v.x * inv, v.y * inv, v.z * inv, v.w * inv};

    if (bx < SS) {
        ushort4 ph;
        unsigned short* hp = &ph.x;
        #pragma unroll
        for (int j = 0; j < 4; j++)
            hp[j] = __half_as_ushort(__float2half(n[j]));
        ((ushort4*)(g_eh + ((size_t)b * SS + bx) * DD))[t] = ph;
    } else {
        unsigned short* base = g_asp16 + (size_t)b * 8 * 2056;
        #pragma unroll
        for (int j = 0; j < 4; j++) {
            unsigned short hu = __half_as_ushort(__float2half(n[j]));
            int eidx = 4 * t + j;
            #pragma unroll
            for (int p = 0; p < 8; p++) {
                int x0 = eidx - p;
                unsigned short* bh = base + p * 2056;
                if (x0 >= 0) bh[x0] = hu;
                int x1 = x0 + 1024;
                if (x1 < 2048) bh[x1] = hu;
            }
        }
    }
}

// ============================ GEMM kernel ============================
// out[b, s_base+m, i_base+n] = sum_k E[m][k] * Circ[n][k]  (single fp16 product)
// E fp16 (A, 3-stage cp.async ring, wait_group 1), Circ fp16 ldsm'd DIRECTLY
// from parity aspect copies. CTA 128x128, 256 thr (8 warps, warp 64x32),
// k-chunk 64, 2 CTAs/SM.
#define ROWA 144                 // 128B payload + 16B pad
#define ASTG (128 * ROWA)        // 18432 per A stage
#define NSTAGE 3
#define OFF_ASP (NSTAGE * ASTG)  // 55296
#define BUFS 4112                // parity buffer stride (bytes)
#define SMEM_DYN (OFF_ASP + 8 * BUFS)   // 88192
#define NCHUNK 16                // 1024 / 64

__global__ void __launch_bounds__(256, 2) gemm_kernel(float* __restrict__ out) {
    extern __shared__ __align__(128) char smem[];
    const uint32_t sbase = smem_u32(smem);
    const uint32_t sAsp = sbase + OFF_ASP;

    const int b      = blockIdx.z;
    const int i_base = blockIdx.x * 128;
    const int s_base = blockIdx.y * 128;
    const int tid  = threadIdx.x;
    const int wid  = tid >> 5;
    const int lane = tid & 31;
    const int wm = wid & 1;      // 2 m-groups of 64
    const int wn = wid >> 1;     // 4 n-groups of 32

    // A loader: thread covers row tid>>1, 64B half (tid&1): 4 x 16B per chunk
    const int r0 = tid >> 1;
    const int h64 = (tid & 1) * 64;
    const char* pA = (const char*)g_eh + ((size_t)b * SS + s_base + r0) * 2048 + h64;
    const uint32_t drowA = sbase + (uint32_t)r0 * ROWA + h64;

    // A ldmatrix lane offset
    const uint32_t a_lane = (uint32_t)(wm * 64 + (lane & 15)) * ROWA + (lane >> 4) * 16;

    // B direct ldmatrix base addresses (lane-dependent, loop-invariant parity)
    uint32_t bA[2];
    #pragma unroll
    for (int p = 0; p < 2; p++) {
        int nidx = wn * 32 + p * 16 + (lane & 7) + 8 * (lane >> 4);
        int kb   = ((lane >> 3) & 1) * 8;
        int s0   = DD + kb - (i_base + nidx);      // >= 1
        int pp   = s0 & 7;
        bA[p] = sAsp + (uint32_t)pp * BUFS + (uint32_t)((s0 >> 3) << 4);
    }

    float acc[4][4][4];
    #pragma unroll
    for (int mt = 0; mt < 4; mt++)
        #pragma unroll
        for (int nt = 0; nt < 4; nt++)
            #pragma unroll
            for (int j = 0; j < 4; j++) acc[mt][nt][j] = 0.f;

    #define LOAD_A(ST, KC) do {                                         \
        uint32_t d_ = drowA + (ST) * ASTG;                              \
        const char* s_ = pA + (size_t)(KC) * 128;                       \
        cpasync16(d_,      s_);                                         \
        cpasync16(d_ + 16, s_ + 16);                                    \
        cpasync16(d_ + 32, s_ + 32);                                    \
        cpasync16(d_ + 48, s_ + 48);                                    \
        asm volatile("cp.async.commit_group;");                         \
    } while (0)

    // ---- prologue: aspect parity copies + A(0) as group, then A(1) ----
    {
        const char* pAsp = (const char*)g_asp16 + (size_t)b * 8 * BUFS;
        for (int j = tid; j < 8 * BUFS / 16; j += 256)
            cpasync16(sAsp + j * 16, pAsp + (size_t)j * 16);
    }
    LOAD_A(0, 0);        // commits aspect + A0 together
    LOAD_A(1, 1);
    asm volatile("cp.async.wait_group 1;" ::: "memory");   // aspect + A0 ready
    __syncthreads();

    uint32_t bcoff = 0;   // B chunk byte offset (+128 per chunk)
    int stg = 0;
    #pragma unroll 3
    for (int c = 0; c < NCHUNK; c++) {
        if (c + 2 < NCHUNK) {
            int ns = stg + 2; if (ns >= NSTAGE) ns -= NSTAGE;
            LOAD_A(ns, c + 2);
        }

        const uint32_t sa = sbase + stg * ASTG;

        #pragma unroll
        for (int kk = 0; kk < 4; kk++) {
            const uint32_t akb = (uint32_t)(kk * 32);
            const uint32_t bkk = bcoff + (uint32_t)(kk * 32);
            uint32_t aH[4][4], bH[2][4];
            #pragma unroll
            for (int mt = 0; mt < 4; mt++)
                ldsm4(aH[mt], sa + a_lane + mt * 16 * ROWA + akb);
            #pragma unroll
            for (int p = 0; p < 2; p++)
                ldsm4(bH[p], bA[p] + bkk);
            #pragma unroll
            for (int mt = 0; mt < 4; mt++)
                #pragma unroll
                for (int nt = 0; nt < 4; nt++)
                    mma16816(acc[mt][nt], aH[mt], &bH[nt >> 1][2 * (nt & 1)]);
        }
        bcoff += 128;

        if (c + 1 < NCHUNK) {
            asm volatile("cp.async.wait_group 1;" ::: "memory");
            __syncthreads();
        }
        stg = (stg + 1 == NSTAGE) ? 0 : stg + 1;
    }

    // ---- epilogue: direct f32 stores ----
    #pragma unroll
    for (int mt = 0; mt < 4; mt++) {
        int rr = s_base + wm * 64 + mt * 16 + (lane >> 2);
        float* p0 = out + ((size_t)b * SS + rr) * DD + i_base + wn * 32 + (lane & 3) * 2;
        float* p1 = p0 + (size_t)8 * DD;
        #pragma unroll
        for (int nt = 0; nt < 4; nt++) {
            *(float2*)(p0 + nt * 8) = make_float2(acc[mt][nt][0], acc[mt][nt][1]);
            *(float2*)(p1 + nt * 8) = make_float2(acc[mt][nt][2], acc[mt][nt][3]);
        }
    }
}

// ============================ launch ============================
extern "C" void kernel_launch(void* const* d_in, const int* in_sizes, int n_in,
                              void* d_out, int out_size) {
    const float* emb = (const float*)d_in[0];   // (32, 512, 1024) f32
    const float* asp = (const float*)d_in[1];   // (32, 1024) f32
    float* out = (float*)d_out;                 // (32, 512, 1024) f32

    cudaFuncSetAttribute(gemm_kernel, cudaFuncAttributeMaxDynamicSharedMemorySize, SMEM_DYN);

    prep_kernel<<<dim3(SS + 1, BB), 256>>>(emb, asp);
    gemm_kernel<<<dim3(DD / 128, SS / 128, BB), 256, SMEM_DYN>>>(out);
}

// round 17
// speedup vs baseline: 1.4678x; 1.0461x over previous
#include <cuda_runtime.h>
#include <cuda_fp16.h>
#include <cstdint>

#define BB 32
#define SS 512
#define DD 1024

// ---- device scratch (module-load allocated; no runtime allocs) ----
// E normalized fp16: [row][k] contiguous (2048B per row)
__device__ unsigned short g_eh[(size_t)BB * SS * DD];       // 32 MB
// aspect parity copies fp16 (hi only): per batch 8 buffers x 2056 u16:
//   buf p: buf[x] = a2[x + p], x in [0,2048), a2[y] = a_norm[y mod 1024]
__device__ __align__(16) unsigned short g_asp16[BB * 8 * 2056];  // 2.1 MB

// ============================ helpers ============================
__device__ __forceinline__ uint32_t smem_u32(const void* p) {
    uint32_t a;
    asm("{ .reg .u64 t; cvta.to.shared.u64 t, %1; cvt.u32.u64 %0, t; }" : "=r"(a) : "l"(p));
    return a;
}
__device__ __forceinline__ void cpasync16(uint32_t dst, const void* src) {
    asm volatile("cp.async.cg.shared.global [%0], [%1], 16;" :: "r"(dst), "l"(src));
}
__device__ __forceinline__ void ldsm4(uint32_t* r, uint32_t a) {
    asm volatile("ldmatrix.sync.aligned.m8n8.x4.shared.b16 {%0,%1,%2,%3}, [%4];"
                 : "=r"(r[0]), "=r"(r[1]), "=r"(r[2]), "=r"(r[3]) : "r"(a));
}
__device__ __forceinline__ void mma16816(float* c, const uint32_t* a, const uint32_t* b) {
    asm volatile(
        "mma.sync.aligned.m16n8k16.row.col.f32.f16.f16.f32 "
        "{%0,%1,%2,%3}, {%4,%5,%6,%7}, {%8,%9}, {%0,%1,%2,%3};"
        : "+f"(c[0]), "+f"(c[1]), "+f"(c[2]), "+f"(c[3])
        : "r"(a[0]), "r"(a[1]), "r"(a[2]), "r"(a[3]), "r"(b[0]), "r"(b[1]));
}

// ============================ prep kernel (fused) ============================
__global__ void prep_kernel(const float* __restrict__ e, const float* __restrict__ a) {
    int bx = blockIdx.x, b = blockIdx.y, t = threadIdx.x;  // 256 threads
    const float* src = (bx < SS) ? (e + ((size_t)b * SS + bx) * DD)
                                 : (a + (size_t)b * DD);
    float4 v = ((const float4*)src)[t];
    float sum = v.x * v.x + v.y * v.y + v.z * v.z + v.w * v.w;
    #pragma unroll
    for (int o = 16; o; o >>= 1) sum += __shfl_xor_sync(0xffffffffu, sum, o);
    __shared__ float ws[8];
    __shared__ float s_inv;
    if ((t & 31) == 0) ws[t >> 5] = sum;
    __syncthreads();
    if (t == 0) {
        float tot = 0.f;
        #pragma unroll
        for (int i = 0; i < 8; i++) tot += ws[i];
        s_inv = (tot > 0.f) ? rsqrtf(tot) : 0.f;
    }
    __syncthreads();
    float inv = s_inv;
    float n[4] = {v.x * inv, v.y * inv, v.z * inv, v.w * inv};

    if (bx < SS) {
        ushort4 ph;
        unsigned short* hp = &ph.x;
        #pragma unroll
        for (int j = 0; j < 4; j++)
            hp[j] = __half_as_ushort(__float2half(n[j]));
        ((ushort4*)(g_eh + ((size_t)b * SS + bx) * DD))[t] = ph;
    } else {
        unsigned short* base = g_asp16 + (size_t)b * 8 * 2056;
        #pragma unroll
        for (int j = 0; j < 4; j++) {
            unsigned short hu = __half_as_ushort(__float2half(n[j]));
            int eidx = 4 * t + j;
            #pragma unroll
            for (int p = 0; p < 8; p++) {
                int x0 = eidx - p;
                unsigned short* bh = base + p * 2056;
                if (x0 >= 0) bh[x0] = hu;
                int x1 = x0 + 1024;
                if (x1 < 2048) bh[x1] = hu;
            }
        }
    }
}

// ============================ GEMM kernel ============================
// out[b, s_base+m, i_base+n] = sum_k E[m][k] * Circ[n][k]  (single fp16 product)
// E fp16 (A, 4-stage cp.async ring, wait_group 2), Circ fp16 ldsm'd DIRECTLY
// from parity aspect copies, with next-chunk B fragment prefetched ACROSS the
// barrier (B is read-only). CTA 128x128, 256 thr (8 warps, warp 64x32),
// k-chunk 64, 2 CTAs/SM.
#define ROWA 144                 // 128B payload + 16B pad
#define ASTG (128 * ROWA)        // 18432 per A stage
#define NSTAGE 4
#define OFF_ASP (NSTAGE * ASTG)  // 73728
#define BUFS 4112                // parity buffer stride (bytes)
#define SMEM_DYN (OFF_ASP + 8 * BUFS)   // 106624
#define NCHUNK 16                // 1024 / 64

__global__ void __launch_bounds__(256, 2) gemm_kernel(float* __restrict__ out) {
    extern __shared__ __align__(128) char smem[];
    const uint32_t sbase = smem_u32(smem);
    const uint32_t sAsp = sbase + OFF_ASP;

    const int b      = blockIdx.z;
    const int i_base = blockIdx.x * 128;
    const int s_base = blockIdx.y * 128;
    const int tid  = threadIdx.x;
    const int wid  = tid >> 5;
    const int lane = tid & 31;
    const int wm = wid & 1;      // 2 m-groups of 64
    const int wn = wid >> 1;     // 4 n-groups of 32

    // A loader: thread covers row tid>>1, 64B half (tid&1): 4 x 16B per chunk
    const int r0 = tid >> 1;
    const int h64 = (tid & 1) * 64;
    const char* pA = (const char*)g_eh + ((size_t)b * SS + s_base + r0) * 2048 + h64;
    const uint32_t drowA = sbase + (uint32_t)r0 * ROWA + h64;

    // A ldmatrix lane offset
    const uint32_t a_lane = (uint32_t)(wm * 64 + (lane & 15)) * ROWA + (lane >> 4) * 16;

    // B direct ldmatrix base addresses (lane-dependent, loop-invariant parity)
    uint32_t bA[2];
    #pragma unroll
    for (int p = 0; p < 2; p++) {
        int nidx = wn * 32 + p * 16 + (lane & 7) + 8 * (lane >> 4);
        int kb   = ((lane >> 3) & 1) * 8;
        int s0   = DD + kb - (i_base + nidx);      // >= 1
        int pp   = s0 & 7;
        bA[p] = sAsp + (uint32_t)pp * BUFS + (uint32_t)((s0 >> 3) << 4);
    }

    float acc[4][4][4];
    #pragma unroll
    for (int mt = 0; mt < 4; mt++)
        #pragma unroll
        for (int nt = 0; nt < 4; nt++)
            #pragma unroll
            for (int j = 0; j < 4; j++) acc[mt][nt][j] = 0.f;

    #define LOAD_A(ST, KC) do {                                         \
        uint32_t d_ = drowA + (ST) * ASTG;                              \
        const char* s_ = pA + (size_t)(KC) * 128;                       \
        cpasync16(d_,      s_);                                         \
        cpasync16(d_ + 16, s_ + 16);                                    \
        cpasync16(d_ + 32, s_ + 32);                                    \
        cpasync16(d_ + 48, s_ + 48);                                    \
        asm volatile("cp.async.commit_group;");                         \
    } while (0)

    // ---- prologue: aspect parity copies + A(0) as group, then A(1), A(2) ----
    {
        const char* pAsp = (const char*)g_asp16 + (size_t)b * 8 * BUFS;
        for (int j = tid; j < 8 * BUFS / 16; j += 256)
            cpasync16(sAsp + j * 16, pAsp + (size_t)j * 16);
    }
    LOAD_A(0, 0);        // commits aspect + A0 together
    LOAD_A(1, 1);
    LOAD_A(2, 2);
    asm volatile("cp.async.wait_group 2;" ::: "memory");   // aspect + A0 ready
    __syncthreads();

    // B prefetch for chunk 0, kk=0
    uint32_t bPre[2][4];
    #pragma unroll
    for (int p = 0; p < 2; p++) ldsm4(bPre[p], bA[p]);

    uint32_t bcoff = 0;   // B chunk byte offset (+128 per chunk)
    int stg = 0;
    #pragma unroll 4
    for (int c = 0; c < NCHUNK; c++) {
        if (c + 3 < NCHUNK) {
            int ns = stg + 3; if (ns >= NSTAGE) ns -= NSTAGE;
            LOAD_A(ns, c + 3);
        }

        const uint32_t sa = sbase + stg * ASTG;

        #pragma unroll
        for (int kk = 0; kk < 4; kk++) {
            const uint32_t akb = (uint32_t)(kk * 32);
            const uint32_t bkk = bcoff + (uint32_t)(kk * 32);
            uint32_t aH[4][4], bH[2][4];
            #pragma unroll
            for (int mt = 0; mt < 4; mt++)
                ldsm4(aH[mt], sa + a_lane + mt * 16 * ROWA + akb);
            if (kk == 0) {
                #pragma unroll
                for (int p = 0; p < 2; p++)
                    #pragma unroll
                    for (int q = 0; q < 4; q++) bH[p][q] = bPre[p][q];
            } else {
                #pragma unroll
                for (int p = 0; p < 2; p++)
                    ldsm4(bH[p], bA[p] + bkk);
            }
            #pragma unroll
            for (int mt = 0; mt < 4; mt++)
                #pragma unroll
                for (int nt = 0; nt < 4; nt++)
                    mma16816(acc[mt][nt], aH[mt], &bH[nt >> 1][2 * (nt & 1)]);
        }
        bcoff += 128;

        if (c + 1 < NCHUNK) {
            // prefetch next chunk's kk=0 B fragments BEFORE the barrier
            #pragma unroll
            for (int p = 0; p < 2; p++) ldsm4(bPre[p], bA[p] + bcoff);
            asm volatile("cp.async.wait_group 2;" ::: "memory");
            __syncthreads();
        }
        stg = (stg + 1 == NSTAGE) ? 0 : stg + 1;
    }

    // ---- epilogue: direct f32 stores ----
    #pragma unroll
    for (int mt = 0; mt < 4; mt++) {
        int rr = s_base + wm * 64 + mt * 16 + (lane >> 2);
        float* p0 = out + ((size_t)b * SS + rr) * DD + i_base + wn * 32 + (lane & 3) * 2;
        float* p1 = p0 + (size_t)8 * DD;
        #pragma unroll
        for (int nt = 0; nt < 4; nt++) {
            *(float2*)(p0 + nt * 8) = make_float2(acc[mt][nt][0], acc[mt][nt][1]);
            *(float2*)(p1 + nt * 8) = make_float2(acc[mt][nt][2], acc[mt][nt][3]);
        }
    }
}

// ============================ launch ============================
extern "C" void kernel_launch(void* const* d_in, const int* in_sizes, int n_in,
                              void* d_out, int out_size) {
    const float* emb = (const float*)d_in[0];   // (32, 512, 1024) f32
    const float* asp = (const float*)d_in[1];   // (32, 1024) f32
    float* out = (float*)d_out;                 // (32, 512, 1024) f32

    cudaFuncSetAttribute(gemm_kernel, cudaFuncAttributeMaxDynamicSharedMemorySize, SMEM_DYN);

    prep_kernel<<<dim3(SS + 1, BB), 256>>>(emb, asp);
    gemm_kernel<<<dim3(DD / 128, SS / 128, BB), 256, SMEM_DYN>>>(out);
}